// round 5
// baseline (speedup 1.0000x reference)
#include <cuda_runtime.h>
#include <cstdint>
#include <cstddef>

#define EPS   1e-6f
#define B_    16
#define NN    1024
#define FDIM  64
#define OUTD  128
#define KC    32
#define NITER (NN / KC)

// smem strides (floats). Conflict-free MMA fragment rules:
//   A-operand stride ≡ 4 (mod 32), B-operand stride ≡ 8 (mod 32)
#define SA_STR 36
#define SX_STR 72
#define OC_STR 196
#define SK_STR 136

// smem layout (float offsets)
#define OFF_ADIAG 0
#define OFF_INV   128
#define OFF_SROW  256
#define OFF_SALL  384
#define OFF_DYN   1408
#define ASTG      (128 * SA_STR)       // 4608
#define XSTG      (32 * SX_STR)        // 2304
#define OFF_A0    OFF_DYN
#define OFF_X0    (OFF_DYN + 3 * ASTG)
#define OFF_OC    OFF_DYN
#define OFF_KM    (OFF_OC + 128 * OC_STR)          // 26496 within dyn
#define SMEM_FLOATS (OFF_KM + 192 * SK_STR)
#define SMEM_BYTES  (SMEM_FLOATS * 4)

__device__ float g_inv[B_ * NN];
__device__ float g_s[B_ * NN];

__device__ __forceinline__ uint32_t smem_u32(const void* p) {
    uint32_t a;
    asm("{ .reg .u64 t; cvta.to.shared.u64 t, %1; cvt.u32.u64 %0, t; }"
        : "=r"(a) : "l"(p));
    return a;
}
__device__ __forceinline__ void cp_async16(uint32_t saddr, const void* g) {
    asm volatile("cp.async.cg.shared.global [%0], [%1], 16;"
                 :: "r"(saddr), "l"(g) : "memory");
}
#define CP_COMMIT() asm volatile("cp.async.commit_group;" ::: "memory")
#define CP_WAIT1()  asm volatile("cp.async.wait_group 1;" ::: "memory")
#define CP_WAIT0()  asm volatile("cp.async.wait_group 0;" ::: "memory")

__device__ __forceinline__ float to_tf32(float v) {
    float r;
    asm("cvt.rna.tf32.f32 %0, %1;" : "=f"(r) : "f"(v));
    return r;
}
__device__ __forceinline__ uint32_t tf32u(float v) {
    return __float_as_uint(to_tf32(v));
}
__device__ __forceinline__ void mma_tf32(float* c, const uint32_t* a, const uint32_t* b) {
    asm volatile(
        "mma.sync.aligned.m16n8k8.row.col.f32.tf32.tf32.f32 "
        "{%0,%1,%2,%3}, {%4,%5,%6,%7}, {%8,%9}, {%0,%1,%2,%3};"
        : "+f"(c[0]), "+f"(c[1]), "+f"(c[2]), "+f"(c[3])
        : "r"(a[0]), "r"(a[1]), "r"(a[2]), "r"(a[3]), "r"(b[0]), "r"(b[1]));
}

// ---------------------------------------------------------------------------
// Kernel 1: degree scalars. deg[b,i] = rowsum(A) - A[i,i] + 1
// ---------------------------------------------------------------------------
__global__ void deg_kernel(const float* __restrict__ A) {
    int warp = (blockIdx.x * blockDim.x + threadIdx.x) >> 5;
    int lane = threadIdx.x & 31;
    if (warp >= B_ * NN) return;
    const float* row = A + (size_t)warp * NN;
    float sum = 0.f;
    const float4* r4 = (const float4*)row;
#pragma unroll
    for (int w = 0; w < 8; w++) {
        float4 v = r4[w * 32 + lane];
        sum += v.x + v.y + v.z + v.w;
    }
#pragma unroll
    for (int off = 16; off > 0; off >>= 1)
        sum += __shfl_down_sync(0xFFFFFFFFu, sum, off);
    if (lane == 0) {
        float deg = sum - row[warp % NN] + 1.0f;
        g_inv[warp] = 1.0f / (EPS + deg);
        g_s[warp]   = 1.0f / (EPS + sqrtf(deg));
    }
}

// ---------------------------------------------------------------------------
// Kernel 2: fully fused, 512 threads, cp.async 3-stage pipeline.
// All MMA operands RNA-rounded to tf32 (in-register for GEMM1 fragments;
// at staging/epilogue-write for GEMM2).
// ---------------------------------------------------------------------------
__global__ __launch_bounds__(512, 1)
void fused_mma_kernel(const float* __restrict__ A, const float* __restrict__ x,
                      const float* __restrict__ Kmat, const float* __restrict__ bias,
                      float* __restrict__ out) {
    extern __shared__ float sm[];
    const uint32_t sb = smem_u32(sm);
    const int tid  = threadIdx.x;
    const int wid  = tid >> 5;
    const int lane = tid & 31;
    const int b    = blockIdx.y;
    const int row0 = blockIdx.x * 128;

    const int wm = wid >> 2;          // 0..3 : 32-row band
    const int wn = wid & 3;           // 0..3 : 32-col band
    const int m_base = wm * 32;
    const int n_base = wn * 32;
    const int lr = lane >> 2;         // 0..7
    const int lc = lane & 3;          // 0..3
    const bool scaled = (wn >= 2);    // this warp computes A@(s*x) columns
    const int f_base = scaled ? (wn - 2) * 32 : n_base;

    const float* Ab = A + (size_t)b * NN * NN;
    const float* xb = x + (size_t)b * NN * FDIM;

    // ---- stage Kmat (tf32-rounded) into smem [192][SK_STR]
    {
        const float4* src = (const float4*)Kmat;
#pragma unroll
        for (int i4 = tid; i4 < 192 * 128 / 4; i4 += 512) {
            int row = i4 >> 5, c4 = (i4 & 31) * 4;
            float4 v = src[i4];
            v.x = to_tf32(v.x); v.y = to_tf32(v.y);
            v.z = to_tf32(v.z); v.w = to_tf32(v.w);
            *(float4*)&sm[OFF_KM + row * SK_STR + c4] = v;
        }
    }
    // ---- per-row scalars + full s vector
#pragma unroll
    for (int i = tid; i < NN; i += 512) sm[OFF_SALL + i] = g_s[b * NN + i];
    if (tid < 128) {
        int grow = row0 + tid;
        sm[OFF_ADIAG + tid] = __ldg(&Ab[(size_t)grow * NN + grow]);
        sm[OFF_INV + tid]   = g_inv[b * NN + grow];
        sm[OFF_SROW + tid]  = g_s[b * NN + grow];
    }

    // ---- cp.async pointer precompute
    const int ar = tid >> 3;             // 0..63
    const int ac = (tid & 7) * 4;
    const int xk = tid >> 4;             // 0..31
    const int xf = (tid & 15) * 4;
    const float* gA = Ab + (size_t)(row0 + ar) * NN + ac;
    const float* gX = xb + (size_t)xk * FDIM + xf;
    uint32_t sA0[3], sA1[3], sX0[3];
#pragma unroll
    for (int s = 0; s < 3; s++) {
        sA0[s] = sb + (OFF_A0 + s * ASTG + ar * SA_STR + ac) * 4;
        sA1[s] = sA0[s] + 64 * SA_STR * 4;
        sX0[s] = sb + (OFF_X0 + s * XSTG + xk * SX_STR + xf) * 4;
    }

    // ---- prologue: issue stages 0 and 1
#pragma unroll
    for (int st = 0; st < 2; st++) {
        const float* ga = gA + st * KC;
        cp_async16(sA0[st], ga);
        cp_async16(sA1[st], ga + (size_t)64 * NN);
        cp_async16(sX0[st], gX + (size_t)st * KC * FDIM);
        CP_COMMIT();
    }

    float acc[2][4][4];
#pragma unroll
    for (int mt = 0; mt < 2; mt++)
#pragma unroll
        for (int nt = 0; nt < 4; nt++)
#pragma unroll
            for (int q = 0; q < 4; q++) acc[mt][nt][q] = 0.f;

    // ---- mainloop
    for (int it = 0; it < NITER; ++it) {
        if (it + 1 < NITER) { CP_WAIT1(); } else { CP_WAIT0(); }
        __syncthreads();
        if (it + 2 < NITER) {
            const int st = it + 2;
            const float* ga = gA + st * KC;
            cp_async16(sA0[st % 3], ga);
            cp_async16(sA1[st % 3], ga + (size_t)64 * NN);
            cp_async16(sX0[st % 3], gX + (size_t)st * KC * FDIM);
            CP_COMMIT();
        }
        const float* sA = &sm[OFF_A0 + (it % 3) * ASTG];
        const float* sX = &sm[OFF_X0 + (it % 3) * XSTG];
        const int kg = it * KC;
#pragma unroll
        for (int ks = 0; ks < 4; ks++) {
            const int k = ks * 8;
            uint32_t af[2][4], bf[4][2];
#pragma unroll
            for (int mt = 0; mt < 2; mt++) {
                const float* p = sA + (m_base + mt * 16 + lr) * SA_STR + k + lc;
                af[mt][0] = tf32u(p[0]);
                af[mt][1] = tf32u(p[8 * SA_STR]);
                af[mt][2] = tf32u(p[4]);
                af[mt][3] = tf32u(p[8 * SA_STR + 4]);
            }
            float s0 = 1.f, s1 = 1.f;
            if (scaled) {
                s0 = sm[OFF_SALL + kg + k + lc];
                s1 = sm[OFF_SALL + kg + k + lc + 4];
            }
#pragma unroll
            for (int nt = 0; nt < 4; nt++) {
                const float* p = sX + (k + lc) * SX_STR + f_base + nt * 8 + lr;
                float b0 = p[0];
                float b1 = p[4 * SX_STR];
                if (scaled) { b0 *= s0; b1 *= s1; }
                bf[nt][0] = tf32u(b0);
                bf[nt][1] = tf32u(b1);
            }
#pragma unroll
            for (int mt = 0; mt < 2; mt++)
#pragma unroll
                for (int nt = 0; nt < 4; nt++)
                    mma_tf32(acc[mt][nt], af[mt], bf[nt]);
        }
    }
    __syncthreads();   // pipeline smem dead; safe to overwrite with ocat

    // ---- epilogue 1: diagonal fix + scalings -> ocat [128][192] (tf32)
#pragma unroll
    for (int mt = 0; mt < 2; mt++) {
#pragma unroll
        for (int nt = 0; nt < 4; nt++) {
            const int f = f_base + nt * 8 + lc * 2;
#pragma unroll
            for (int h = 0; h < 2; h++) {
                const int r = m_base + mt * 16 + lr + h * 8;
                const float ad  = sm[OFF_ADIAG + r];
                const float c0 = acc[mt][nt][h * 2 + 0];
                const float c1 = acc[mt][nt][h * 2 + 1];
                float2 xv = *(const float2*)&xb[(size_t)(row0 + r) * FDIM + f];
                if (!scaled) {
                    const float inv = sm[OFF_INV + r];
                    float o1a = c0 - ad * xv.x;
                    float o1b = c1 - ad * xv.y;
                    float2 w1 = make_float2(to_tf32(o1a), to_tf32(o1b));
                    float2 w2 = make_float2(to_tf32(inv * (o1a + xv.x)),
                                            to_tf32(inv * (o1b + xv.y)));
                    *(float2*)&sm[OFF_OC + r * OC_STR + f]      = w1;
                    *(float2*)&sm[OFF_OC + r * OC_STR + 64 + f] = w2;
                } else {
                    const float sv = sm[OFF_SROW + r];
                    const float t = sv * sv * (1.0f - ad);
                    float2 w3 = make_float2(to_tf32(sv * c0 + t * xv.x),
                                            to_tf32(sv * c1 + t * xv.y));
                    *(float2*)&sm[OFF_OC + r * OC_STR + 128 + f] = w3;
                }
            }
        }
    }
    __syncthreads();

    // ---- GEMM2: out[128,128] = ocat[128,192] @ Kmat[192,128]
#pragma unroll
    for (int mt = 0; mt < 2; mt++)
#pragma unroll
        for (int nt = 0; nt < 4; nt++)
#pragma unroll
            for (int q = 0; q < 4; q++) acc[mt][nt][q] = 0.f;

#pragma unroll
    for (int ks = 0; ks < 24; ks++) {
        const int k = ks * 8;
        uint32_t af[2][4], bf[4][2];
#pragma unroll
        for (int mt = 0; mt < 2; mt++) {
            const float* p = &sm[OFF_OC + (m_base + mt * 16 + lr) * OC_STR + k + lc];
            af[mt][0] = __float_as_uint(p[0]);
            af[mt][1] = __float_as_uint(p[8 * OC_STR]);
            af[mt][2] = __float_as_uint(p[4]);
            af[mt][3] = __float_as_uint(p[8 * OC_STR + 4]);
        }
#pragma unroll
        for (int nt = 0; nt < 4; nt++) {
            const float* p = &sm[OFF_KM + (k + lc) * SK_STR + n_base + nt * 8 + lr];
            bf[nt][0] = __float_as_uint(p[0]);
            bf[nt][1] = __float_as_uint(p[4 * SK_STR]);
        }
#pragma unroll
        for (int mt = 0; mt < 2; mt++)
#pragma unroll
            for (int nt = 0; nt < 4; nt++)
                mma_tf32(acc[mt][nt], af[mt], bf[nt]);
    }

    // ---- bias + relu + store
#pragma unroll
    for (int mt = 0; mt < 2; mt++) {
#pragma unroll
        for (int nt = 0; nt < 4; nt++) {
            const int col = n_base + nt * 8 + lc * 2;
            float2 bv = *(const float2*)&bias[col];
#pragma unroll
            for (int h = 0; h < 2; h++) {
                const int r = m_base + mt * 16 + lr + h * 8;
                float2 o;
                o.x = fmaxf(acc[mt][nt][h * 2 + 0] + bv.x, 0.f);
                o.y = fmaxf(acc[mt][nt][h * 2 + 1] + bv.y, 0.f);
                *(float2*)&out[((size_t)b * NN + row0 + r) * OUTD + col] = o;
            }
        }
    }
}

// ---------------------------------------------------------------------------
extern "C" void kernel_launch(void* const* d_in, const int* in_sizes, int n_in,
                              void* d_out, int out_size) {
    const float *x = nullptr, *A = nullptr, *Kmat = nullptr, *bias = nullptr;
    for (int i = 0; i < n_in; i++) {
        switch (in_sizes[i]) {
            case B_ * NN * FDIM:  x    = (const float*)d_in[i]; break;
            case B_ * NN * NN:    A    = (const float*)d_in[i]; break;
            case 3 * FDIM * OUTD: Kmat = (const float*)d_in[i]; break;
            case OUTD:            bias = (const float*)d_in[i]; break;
        }
    }
    float* out = (float*)d_out;

    static bool attr_set = false;
    if (!attr_set) {
        cudaFuncSetAttribute(fused_mma_kernel,
                             cudaFuncAttributeMaxDynamicSharedMemorySize, SMEM_BYTES);
        attr_set = true;
    }

    deg_kernel<<<(B_ * NN * 32 + 255) / 256, 256>>>(A);
    fused_mma_kernel<<<dim3(NN / 128, B_), 512, SMEM_BYTES>>>(A, x, Kmat, bias, out);
}

// round 6
// speedup vs baseline: 1.0957x; 1.0957x over previous
#include <cuda_runtime.h>
#include <cstdint>
#include <cstddef>

#define EPS   1e-6f
#define B_    16
#define NN    1024
#define FDIM  64
#define OUTD  128
#define KC    32
#define NITER (NN / KC)

// smem strides (floats). Conflict-free MMA fragment rules:
//   A-operand stride ≡ 4 (mod 32), B-operand stride ≡ 8 (mod 32)
#define SA_STR 36
#define SB_STR 136
#define OC_STR 196
#define SK_STR 136

// smem layout (float offsets)
#define OFF_ADIAG 0
#define OFF_INV   128
#define OFF_SROW  256
#define OFF_SALL  384
#define OFF_DYN   1408
#define ASTG      (128 * SA_STR)          // 4608
#define BSTG      (32 * SB_STR)           // 4352
#define OFF_A0    OFF_DYN
#define OFF_A1    (OFF_A0 + ASTG)
#define OFF_B0    (OFF_A1 + ASTG)
#define OFF_B1    (OFF_B0 + BSTG)
#define OFF_OC    OFF_DYN                              // reuses pipeline space
#define OFF_KM    (OFF_OC + 128 * OC_STR)              // 26496 (above pipeline top 19328)
#define SMEM_FLOATS (OFF_KM + 192 * SK_STR)            // 52608
#define SMEM_BYTES  (SMEM_FLOATS * 4)                  // 210432

__device__ float g_inv[B_ * NN];
__device__ float g_s[B_ * NN];

__device__ __forceinline__ float to_tf32(float v) {
    float r;
    asm("cvt.rna.tf32.f32 %0, %1;" : "=f"(r) : "f"(v));
    return r;
}
__device__ __forceinline__ float4 tf32x4(float4 v) {
    v.x = to_tf32(v.x); v.y = to_tf32(v.y);
    v.z = to_tf32(v.z); v.w = to_tf32(v.w);
    return v;
}
__device__ __forceinline__ void mma_tf32(float* c, const uint32_t* a, const uint32_t* b) {
    asm volatile(
        "mma.sync.aligned.m16n8k8.row.col.f32.tf32.tf32.f32 "
        "{%0,%1,%2,%3}, {%4,%5,%6,%7}, {%8,%9}, {%0,%1,%2,%3};"
        : "+f"(c[0]), "+f"(c[1]), "+f"(c[2]), "+f"(c[3])
        : "r"(a[0]), "r"(a[1]), "r"(a[2]), "r"(a[3]), "r"(b[0]), "r"(b[1]));
}

// ---------------------------------------------------------------------------
// Kernel 1: degree scalars. deg[b,i] = rowsum(A) - A[i,i] + 1
// ---------------------------------------------------------------------------
__global__ void deg_kernel(const float* __restrict__ A) {
    int warp = (blockIdx.x * blockDim.x + threadIdx.x) >> 5;
    int lane = threadIdx.x & 31;
    if (warp >= B_ * NN) return;
    const float* row = A + (size_t)warp * NN;
    float sum = 0.f;
    const float4* r4 = (const float4*)row;
#pragma unroll
    for (int w = 0; w < 8; w++) {
        float4 v = r4[w * 32 + lane];
        sum += v.x + v.y + v.z + v.w;
    }
#pragma unroll
    for (int off = 16; off > 0; off >>= 1)
        sum += __shfl_down_sync(0xFFFFFFFFu, sum, off);
    if (lane == 0) {
        float deg = sum - row[warp % NN] + 1.0f;
        g_inv[warp] = 1.0f / (EPS + deg);
        g_s[warp]   = 1.0f / (EPS + sqrtf(deg));
    }
}

// ---------------------------------------------------------------------------
// Kernel 2: fully fused, 512 threads. Register-staged double buffer;
// all tf32 conversions happen ONCE per element at staging. Inner loop is
// pure LDS + MMA.
// ---------------------------------------------------------------------------
__global__ __launch_bounds__(512, 1)
void fused_mma_kernel(const float* __restrict__ A, const float* __restrict__ x,
                      const float* __restrict__ Kmat, const float* __restrict__ bias,
                      float* __restrict__ out) {
    extern __shared__ float sm[];
    const int tid  = threadIdx.x;
    const int wid  = tid >> 5;
    const int lane = tid & 31;
    const int b    = blockIdx.y;
    const int row0 = blockIdx.x * 128;

    const int wm = wid >> 2;          // 0..3 : 32-row band
    const int wn = wid & 3;           // 0..3 : 32-col band of D
    const int m_base = wm * 32;
    const int n_base = wn * 32;
    const int lr = lane >> 2;         // 0..7
    const int lc = lane & 3;          // 0..3
    const bool scaled = (wn >= 2);    // D cols 64..127 = A@(s*x)
    const int f_base = scaled ? (wn - 2) * 32 : n_base;        // x feature base
    const int b_base = scaled ? 64 + f_base : f_base;          // col in B tile

    const float* Ab = A + (size_t)b * NN * NN;
    const float* xb = x + (size_t)b * NN * FDIM;

    // ---- stage Kmat (tf32) into smem [192][SK_STR]
    {
        const float4* src = (const float4*)Kmat;
#pragma unroll
        for (int i4 = tid; i4 < 192 * 128 / 4; i4 += 512) {
            int row = i4 >> 5, c4 = (i4 & 31) * 4;
            *(float4*)&sm[OFF_KM + row * SK_STR + c4] = tf32x4(src[i4]);
        }
    }
    // ---- per-row scalars + full s vector
#pragma unroll
    for (int i = tid; i < NN; i += 512) sm[OFF_SALL + i] = g_s[b * NN + i];
    if (tid < 128) {
        int grow = row0 + tid;
        sm[OFF_ADIAG + tid] = __ldg(&Ab[(size_t)grow * NN + grow]);
        sm[OFF_INV + tid]   = g_inv[b * NN + grow];
        sm[OFF_SROW + tid]  = g_s[b * NN + grow];
    }
    __syncthreads();   // SALL visible for staging

    // ---- staging geometry
    const int ar = tid >> 3;            // 0..63 (A row; +64 for 2nd chunk)
    const int ac = (tid & 7) * 4;       // A col within k-tile
    const int xk = tid >> 4;            // 0..31 (x row within k-tile)
    const int xf = (tid & 15) * 4;      // x feature
    const float* gA0 = Ab + (size_t)(row0 + ar) * NN + ac;
    const float* gA1 = gA0 + (size_t)64 * NN;
    const float* gX  = xb + (size_t)xk * FDIM + xf;
    const int sa_off = ar * SA_STR + ac;
    const int sb_off = xk * SB_STR + xf;

    float acc[2][4][4];
#pragma unroll
    for (int mt = 0; mt < 2; mt++)
#pragma unroll
        for (int nt = 0; nt < 4; nt++)
#pragma unroll
            for (int q = 0; q < 4; q++) acc[mt][nt][q] = 0.f;

    // ---- prologue: tile 0 -> buf0
    {
        float4 a0 = *(const float4*)gA0;
        float4 a1 = *(const float4*)gA1;
        float4 xv = *(const float4*)gX;
        float  sv = sm[OFF_SALL + xk];
        *(float4*)&sm[OFF_A0 + sa_off]                 = tf32x4(a0);
        *(float4*)&sm[OFF_A0 + sa_off + 64 * SA_STR]   = tf32x4(a1);
        float4 w = make_float4(sv * xv.x, sv * xv.y, sv * xv.z, sv * xv.w);
        *(float4*)&sm[OFF_B0 + sb_off]      = tf32x4(xv);
        *(float4*)&sm[OFF_B0 + sb_off + 64] = tf32x4(w);
    }
    __syncthreads();

    // ---- mainloop: 1 sync/iter, register double buffer
    for (int it = 0; it < NITER; ++it) {
        float4 a0, a1, xv;
        float  sv;
        const bool haveNext = (it + 1 < NITER);
        if (haveNext) {
            const int kn = (it + 1) * KC;
            a0 = *(const float4*)(gA0 + kn);
            a1 = *(const float4*)(gA1 + kn);
            xv = *(const float4*)(gX + (size_t)kn * FDIM);
            sv = sm[OFF_SALL + kn + xk];
        }
        const float* sA = &sm[(it & 1) ? OFF_A1 : OFF_A0];
        const float* sB = &sm[(it & 1) ? OFF_B1 : OFF_B0];
#pragma unroll
        for (int ks = 0; ks < 4; ks++) {
            const int k = ks * 8;
            uint32_t af[2][4], bf[4][2];
#pragma unroll
            for (int mt = 0; mt < 2; mt++) {
                const float* p = sA + (m_base + mt * 16 + lr) * SA_STR + k + lc;
                af[mt][0] = __float_as_uint(p[0]);
                af[mt][1] = __float_as_uint(p[8 * SA_STR]);
                af[mt][2] = __float_as_uint(p[4]);
                af[mt][3] = __float_as_uint(p[8 * SA_STR + 4]);
            }
#pragma unroll
            for (int nt = 0; nt < 4; nt++) {
                const float* p = sB + (k + lc) * SB_STR + b_base + nt * 8 + lr;
                bf[nt][0] = __float_as_uint(p[0]);
                bf[nt][1] = __float_as_uint(p[4 * SB_STR]);
            }
#pragma unroll
            for (int mt = 0; mt < 2; mt++)
#pragma unroll
                for (int nt = 0; nt < 4; nt++)
                    mma_tf32(acc[mt][nt], af[mt], bf[nt]);
        }
        if (haveNext) {
            const int da = (it & 1) ? OFF_A0 : OFF_A1;
            const int db = (it & 1) ? OFF_B0 : OFF_B1;
            *(float4*)&sm[da + sa_off]               = tf32x4(a0);
            *(float4*)&sm[da + sa_off + 64 * SA_STR] = tf32x4(a1);
            float4 w = make_float4(sv * xv.x, sv * xv.y, sv * xv.z, sv * xv.w);
            *(float4*)&sm[db + sb_off]      = tf32x4(xv);
            *(float4*)&sm[db + sb_off + 64] = tf32x4(w);
        }
        __syncthreads();
    }

    // ---- epilogue 1: analytic diagonal fix + scalings -> ocat [128][192]
#pragma unroll
    for (int mt = 0; mt < 2; mt++) {
#pragma unroll
        for (int nt = 0; nt < 4; nt++) {
            const int f = f_base + nt * 8 + lc * 2;
#pragma unroll
            for (int h = 0; h < 2; h++) {
                const int r = m_base + mt * 16 + lr + h * 8;
                const float ad = sm[OFF_ADIAG + r];
                const float c0 = acc[mt][nt][h * 2 + 0];
                const float c1 = acc[mt][nt][h * 2 + 1];
                float2 xv = *(const float2*)&xb[(size_t)(row0 + r) * FDIM + f];
                if (!scaled) {
                    const float inv = sm[OFF_INV + r];
                    float o1a = c0 - ad * xv.x;
                    float o1b = c1 - ad * xv.y;
                    float2 w1 = make_float2(to_tf32(o1a), to_tf32(o1b));
                    float2 w2 = make_float2(to_tf32(inv * (o1a + xv.x)),
                                            to_tf32(inv * (o1b + xv.y)));
                    *(float2*)&sm[OFF_OC + r * OC_STR + f]      = w1;
                    *(float2*)&sm[OFF_OC + r * OC_STR + 64 + f] = w2;
                } else {
                    const float sv = sm[OFF_SROW + r];
                    const float t = sv * sv * (1.0f - ad);
                    float2 w3 = make_float2(to_tf32(sv * c0 + t * xv.x),
                                            to_tf32(sv * c1 + t * xv.y));
                    *(float2*)&sm[OFF_OC + r * OC_STR + 128 + f] = w3;
                }
            }
        }
    }
    __syncthreads();

    // ---- GEMM2: out[128,128] = ocat[128,192] @ Kmat[192,128]
#pragma unroll
    for (int mt = 0; mt < 2; mt++)
#pragma unroll
        for (int nt = 0; nt < 4; nt++)
#pragma unroll
            for (int q = 0; q < 4; q++) acc[mt][nt][q] = 0.f;

#pragma unroll
    for (int ks = 0; ks < 24; ks++) {
        const int k = ks * 8;
        uint32_t af[2][4], bf[4][2];
#pragma unroll
        for (int mt = 0; mt < 2; mt++) {
            const float* p = &sm[OFF_OC + (m_base + mt * 16 + lr) * OC_STR + k + lc];
            af[mt][0] = __float_as_uint(p[0]);
            af[mt][1] = __float_as_uint(p[8 * OC_STR]);
            af[mt][2] = __float_as_uint(p[4]);
            af[mt][3] = __float_as_uint(p[8 * OC_STR + 4]);
        }
#pragma unroll
        for (int nt = 0; nt < 4; nt++) {
            const float* p = &sm[OFF_KM + (k + lc) * SK_STR + n_base + nt * 8 + lr];
            bf[nt][0] = __float_as_uint(p[0]);
            bf[nt][1] = __float_as_uint(p[4 * SK_STR]);
        }
#pragma unroll
        for (int mt = 0; mt < 2; mt++)
#pragma unroll
            for (int nt = 0; nt < 4; nt++)
                mma_tf32(acc[mt][nt], af[mt], bf[nt]);
    }

    // ---- bias + relu + store
#pragma unroll
    for (int mt = 0; mt < 2; mt++) {
#pragma unroll
        for (int nt = 0; nt < 4; nt++) {
            const int col = n_base + nt * 8 + lc * 2;
            float2 bv = *(const float2*)&bias[col];
#pragma unroll
            for (int h = 0; h < 2; h++) {
                const int r = m_base + mt * 16 + lr + h * 8;
                float2 o;
                o.x = fmaxf(acc[mt][nt][h * 2 + 0] + bv.x, 0.f);
                o.y = fmaxf(acc[mt][nt][h * 2 + 1] + bv.y, 0.f);
                *(float2*)&out[((size_t)b * NN + row0 + r) * OUTD + col] = o;
            }
        }
    }
}

// ---------------------------------------------------------------------------
extern "C" void kernel_launch(void* const* d_in, const int* in_sizes, int n_in,
                              void* d_out, int out_size) {
    const float *x = nullptr, *A = nullptr, *Kmat = nullptr, *bias = nullptr;
    for (int i = 0; i < n_in; i++) {
        switch (in_sizes[i]) {
            case B_ * NN * FDIM:  x    = (const float*)d_in[i]; break;
            case B_ * NN * NN:    A    = (const float*)d_in[i]; break;
            case 3 * FDIM * OUTD: Kmat = (const float*)d_in[i]; break;
            case OUTD:            bias = (const float*)d_in[i]; break;
        }
    }
    float* out = (float*)d_out;

    static bool attr_set = false;
    if (!attr_set) {
        cudaFuncSetAttribute(fused_mma_kernel,
                             cudaFuncAttributeMaxDynamicSharedMemorySize, SMEM_BYTES);
        attr_set = true;
    }

    deg_kernel<<<(B_ * NN * 32 + 255) / 256, 256>>>(A);
    fused_mma_kernel<<<dim3(NN / 128, B_), 512, SMEM_BYTES>>>(A, x, Kmat, bias, out);
}